// round 3
// baseline (speedup 1.0000x reference)
#include <cuda_runtime.h>

#define NPIX   9216      // 96*96
#define HW_    96
#define CIN_   256
#define EMB1_  256
#define EMB2_  128
#define NCLS_  80
#define NEG_   3
#define BATCH_ 8

// scratch (allocation-free: __device__ globals)
__device__ float g_h   [(size_t)BATCH_ * EMB1_ * NPIX];   // conv1+BN output
__device__ float g_emb [(size_t)BATCH_ * EMB2_ * NPIX];   // conv2 output, normalized in-place
__device__ float g_reps[NCLS_ * EMB2_];                   // normalized positive reps
__device__ float g_repsneg[NCLS_ * NEG_ * EMB2_];         // normalized negative reps [c][n][e]

// ---------------------------------------------------------------------------
// 3x3 SAME conv, direct. Tile: 32 (x) by 8 (y) pixels, 32 output channels.
// 256 threads, thread = one pixel, 32 oc accumulators.
// STAGE 1: x -> g_h with BN folded.  STAGE 2: g_h -> g_emb (bias only).
// ---------------------------------------------------------------------------
template<int CIN, int CO, int STAGE>
__global__ __launch_bounds__(256)
void conv3x3_v3(const float* __restrict__ xin,
                const float* __restrict__ w,
                const float* __restrict__ bias,
                const float* __restrict__ gamma,
                const float* __restrict__ beta,
                const float* __restrict__ mean,
                const float* __restrict__ var)
{
    __shared__ float xs[10 * 34];                 // halo tile: rows ty-1..ty+8, cols tx-1..tx+32
    __shared__ __align__(16) float ws[9 * 32];    // [k][co]

    const int tid = threadIdx.x;
    const int px  = tid & 31;          // 0..31
    const int py  = tid >> 5;          // 0..7
    const int tx  = (blockIdx.x % 3) * 32;
    const int ty  = (blockIdx.x / 3) * 8;
    const int b   = blockIdx.y;
    const int co0 = blockIdx.z * 32;

    const float* xb = ((STAGE == 1) ? xin : (const float*)g_h) + (size_t)b * CIN * NPIX;

    float acc[32];
#pragma unroll
    for (int i = 0; i < 32; ++i) acc[i] = 0.f;

    for (int ci = 0; ci < CIN; ++ci) {
        // halo: 10 rows x 34 cols = 340 entries (strided full-coverage loop)
        for (int i = tid; i < 340; i += 256) {
            int r = i / 34, c = i - r * 34;
            int gy = ty + r - 1, gx = tx + c - 1;
            float v = 0.f;
            if ((unsigned)gy < 96u && (unsigned)gx < 96u)
                v = xb[(size_t)ci * NPIX + gy * HW_ + gx];
            xs[i] = v;
        }
        // weights: 288 entries — MUST be a strided loop (288 > blockDim=256)
        for (int i = tid; i < 288; i += 256) {
            int k = i >> 5, co = i & 31;
            ws[i] = w[((size_t)(co0 + co) * CIN + ci) * 9 + k];
        }
        __syncthreads();

        float xr[9];
#pragma unroll
        for (int kr = 0; kr < 3; ++kr)
#pragma unroll
            for (int kc = 0; kc < 3; ++kc)
                xr[kr * 3 + kc] = xs[(py + kr) * 34 + px + kc];

#pragma unroll
        for (int k = 0; k < 9; ++k) {
            float xv = xr[k];
            const float4* w4 = reinterpret_cast<const float4*>(&ws[k * 32]);
#pragma unroll
            for (int q = 0; q < 8; ++q) {
                float4 wv = w4[q];
                acc[q * 4 + 0] = fmaf(wv.x, xv, acc[q * 4 + 0]);
                acc[q * 4 + 1] = fmaf(wv.y, xv, acc[q * 4 + 1]);
                acc[q * 4 + 2] = fmaf(wv.z, xv, acc[q * 4 + 2]);
                acc[q * 4 + 3] = fmaf(wv.w, xv, acc[q * 4 + 3]);
            }
        }
        __syncthreads();
    }

    float* outp = (STAGE == 1) ? g_h : g_emb;
    const size_t pix = (size_t)(ty + py) * HW_ + (tx + px);
#pragma unroll
    for (int co = 0; co < 32; ++co) {
        int oc = co0 + co;
        float v = acc[co] + bias[oc];
        if (STAGE == 1) {
            float sc = gamma[oc] * rsqrtf(var[oc] + 1e-5f);
            v = (v - mean[oc]) * sc + beta[oc];
        }
        outp[((size_t)b * CO + oc) * NPIX + pix] = v;
    }
}

// ---------------------------------------------------------------------------
// L2-normalize emb over channels, in place. One thread per pixel.
// ---------------------------------------------------------------------------
__global__ __launch_bounds__(256)
void normalize_emb_kernel()
{
    const int p = blockIdx.x * 256 + threadIdx.x;   // 0..9215 (36 blocks)
    const int b = blockIdx.y;
    float ss = 0.f;
#pragma unroll 8
    for (int ch = 0; ch < EMB2_; ++ch) {
        float v = g_emb[((size_t)b * EMB2_ + ch) * NPIX + p];
        ss = fmaf(v, v, ss);
    }
    float sc = 1.f / fmaxf(sqrtf(ss), 1e-12f);
#pragma unroll 8
    for (int ch = 0; ch < EMB2_; ++ch) {
        size_t idx = ((size_t)b * EMB2_ + ch) * NPIX + p;
        g_emb[idx] = g_emb[idx] * sc;
    }
}

// ---------------------------------------------------------------------------
// reps prep: block per class, 128 threads, shuffle reductions.
// ---------------------------------------------------------------------------
__device__ __forceinline__ float block_sumsq_128(float v, float* red4)
{
    float s = v * v;
#pragma unroll
    for (int o = 16; o > 0; o >>= 1) s += __shfl_xor_sync(0xffffffffu, s, o);
    const int wid = threadIdx.x >> 5, lane = threadIdx.x & 31;
    if (lane == 0) red4[wid] = s;
    __syncthreads();
    float tot = red4[0] + red4[1] + red4[2] + red4[3];
    __syncthreads();
    return tot;
}

__global__ __launch_bounds__(128)
void prep_reps_v3(const float* __restrict__ rep_w,
                  const float* __restrict__ rep_b,
                  const float* __restrict__ neg_w,
                  const float* __restrict__ neg_b)
{
    __shared__ float r_s[128];
    __shared__ float h_a[128];
    __shared__ float h_b[128];
    __shared__ float red4[4];

    const int j = threadIdx.x, c = blockIdx.x;

    float v = rep_w[c * 128 + j] + rep_b[c * 128 + j];
    float tot = block_sumsq_128(v, red4);
    float scale = 1.f / fmaxf(sqrtf(tot), 1e-12f);
    r_s[j] = v * scale;
    g_reps[c * 128 + j] = v * scale;
    __syncthreads();

    for (int n = 0; n < NEG_; ++n) {
        float accf = 0.f;
        const float* src = r_s;
#pragma unroll
        for (int i = 0; i < 3; ++i) {
            const float* W = neg_w + (size_t)((n * 3 + i) * 128) * 128;  // [j][k]
            float acc = neg_b[(n * 3 + i) * 128 + j];
            for (int k = 0; k < 128; ++k)
                acc = fmaf(src[k], W[(size_t)j * 128 + k], acc);
            if (i < 2) {
                acc = fmaxf(acc, 0.f);
                float* dst = (i == 0) ? h_a : h_b;
                dst[j] = acc;
                __syncthreads();
                src = dst;
            } else {
                accf = acc;
            }
        }
        float t2 = block_sumsq_128(accf, red4);
        float sc2 = 1.f / fmaxf(sqrtf(t2), 1e-12f);
        g_repsneg[((size_t)c * NEG_ + n) * 128 + j] = accf * sc2;
        __syncthreads();
    }
}

// ---------------------------------------------------------------------------
// dot + epilogue: 64-pixel x 16-class tile; emb already normalized.
// thread = 1 class x 4 pixels. Writes all 5 outputs.
// ---------------------------------------------------------------------------
__global__ __launch_bounds__(256)
void dot_out_v3(float* __restrict__ out)
{
    extern __shared__ float sm[];
    float* e_s  = sm;                 // [128 ch][64 px]
    float* rp_s = sm + 8192;          // [16 cls][128]
    float* rn_s = sm + 8192 + 2048;   // [16 cls][3][128]

    const int tid = threadIdx.x;
    const int b  = blockIdx.y;
    const int p0 = blockIdx.x * 64;
    const int c0 = blockIdx.z * 16;

    for (int i = tid; i < 8192; i += 256) {
        int ch = i >> 6, p = i & 63;
        e_s[i] = g_emb[((size_t)b * EMB2_ + ch) * NPIX + p0 + p];
    }
    for (int i = tid; i < 2048; i += 256) rp_s[i] = g_reps[c0 * EMB2_ + i];
    for (int i = tid; i < 6144; i += 256) rn_s[i] = g_repsneg[c0 * NEG_ * EMB2_ + i];
    __syncthreads();

    const int cc = tid >> 4;       // class within chunk (0..15)
    const int pg = tid & 15;       // pixel group of 4 (0..15)
    const float* rpp = rp_s + cc * 128;
    const float* rn0 = rn_s + (cc * 3 + 0) * 128;
    const float* rn1 = rn_s + (cc * 3 + 1) * 128;
    const float* rn2 = rn_s + (cc * 3 + 2) * 128;

    float ap[4] = {0, 0, 0, 0};
    float a0[4] = {0, 0, 0, 0};
    float a1[4] = {0, 0, 0, 0};
    float a2[4] = {0, 0, 0, 0};

#pragma unroll 4
    for (int ch = 0; ch < 128; ++ch) {
        float4 ev = *reinterpret_cast<const float4*>(&e_s[ch * 64 + pg * 4]);
        float wp = rpp[ch], w0 = rn0[ch], w1 = rn1[ch], w2 = rn2[ch];
        ap[0] = fmaf(ev.x, wp, ap[0]); ap[1] = fmaf(ev.y, wp, ap[1]);
        ap[2] = fmaf(ev.z, wp, ap[2]); ap[3] = fmaf(ev.w, wp, ap[3]);
        a0[0] = fmaf(ev.x, w0, a0[0]); a0[1] = fmaf(ev.y, w0, a0[1]);
        a0[2] = fmaf(ev.z, w0, a0[2]); a0[3] = fmaf(ev.w, w0, a0[3]);
        a1[0] = fmaf(ev.x, w1, a1[0]); a1[1] = fmaf(ev.y, w1, a1[1]);
        a1[2] = fmaf(ev.z, w1, a1[2]); a1[3] = fmaf(ev.w, w1, a1[3]);
        a2[0] = fmaf(ev.x, w2, a2[0]); a2[1] = fmaf(ev.y, w2, a2[1]);
        a2[2] = fmaf(ev.z, w2, a2[2]); a2[3] = fmaf(ev.w, w2, a2[3]);
    }

    const int c = c0 + cc;
    const size_t S = (size_t)BATCH_ * NCLS_ * NPIX;   // 5898240
    float* out_cls  = out;            // (B,C,H,W)
    float* out_csn  = out + S;        // (B,C,H,W)
    float* out_dist = out + 2 * S;    // (B,C,1,H,W)
    float* out_dneg = out + 3 * S;    // (B,C,3,H,W) -> 3S
    float* out_pori = out + 6 * S;    // (B,C,H,W)

    const size_t base   = ((size_t)b * NCLS_ + c) * NPIX + p0 + pg * 4;
    const size_t dnbase = ((size_t)(b * NCLS_ + c) * 3) * NPIX + p0 + pg * 4;

#pragma unroll
    for (int jx = 0; jx < 4; ++jx) {
        float dist = sqrtf(fmaxf(2.f - 2.f * ap[jx], 0.f));
        float dn0  = sqrtf(fmaxf(2.f - 2.f * a0[jx], 0.f));
        float dn1  = sqrtf(fmaxf(2.f - 2.f * a1[jx], 0.f));
        float dn2  = sqrtf(fmaxf(2.f - 2.f * a2[jx], 0.f));

        // inv2s2 = 1/(2*0.5^2) = 2.0
        float pn0 = expf(-dn0 * dn0 * 2.f);
        float pn1 = expf(-dn1 * dn1 * 2.f);
        float pn2 = expf(-dn2 * dn2 * 2.f);
        float csn = fmaxf(pn0, fmaxf(pn1, pn2));

        float minn = fminf(dn0, fminf(dn1, dn2));
        float shifted = dist + 0.3f * fmaxf(2.f - minn, 0.f);
        float pr = expf(-shifted * shifted * 2.f);
        float cs = fminf(fmaxf(pr, 0.f), 1.f);
        float cls = logf(fmaxf(cs, 1e-5f) / fmaxf(1.f - cs, 1e-5f));
        float pori = expf(-dist * dist * 2.f);

        out_cls [base + jx] = cls;
        out_csn [base + jx] = csn;
        out_dist[base + jx] = dist;
        out_pori[base + jx] = pori;
        out_dneg[dnbase + jx]            = dn0;
        out_dneg[dnbase + NPIX + jx]     = dn1;
        out_dneg[dnbase + 2 * NPIX + jx] = dn2;
    }
}

// ---------------------------------------------------------------------------
extern "C" void kernel_launch(void* const* d_in, const int* in_sizes, int n_in,
                              void* d_out, int out_size)
{
    const float* x      = (const float*)d_in[0];
    const float* w1     = (const float*)d_in[1];
    const float* b1     = (const float*)d_in[2];
    const float* gamma  = (const float*)d_in[3];
    const float* beta   = (const float*)d_in[4];
    const float* mean   = (const float*)d_in[5];
    const float* var    = (const float*)d_in[6];
    const float* w2     = (const float*)d_in[7];
    const float* b2     = (const float*)d_in[8];
    const float* rep_w  = (const float*)d_in[9];
    const float* rep_b  = (const float*)d_in[10];
    const float* neg_w  = (const float*)d_in[11];
    const float* neg_b  = (const float*)d_in[12];
    float* out = (float*)d_out;

    (void)in_sizes; (void)n_in; (void)out_size;

    cudaFuncSetAttribute(dot_out_v3,
                         cudaFuncAttributeMaxDynamicSharedMemorySize, 65536);

    // conv1 + BN
    conv3x3_v3<CIN_, EMB1_, 1><<<dim3(36, BATCH_, EMB1_ / 32), 256>>>(
        x, w1, b1, gamma, beta, mean, var);

    // reps + negative MLPs (independent of convs)
    prep_reps_v3<<<NCLS_, 128>>>(rep_w, rep_b, neg_w, neg_b);

    // conv2
    conv3x3_v3<EMB1_, EMB2_, 2><<<dim3(36, BATCH_, EMB2_ / 32), 256>>>(
        nullptr, w2, b2, nullptr, nullptr, nullptr, nullptr);

    // explicit L2 normalization of emb
    normalize_emb_kernel<<<dim3(36, BATCH_), 256>>>();

    // fused dot + all outputs
    dot_out_v3<<<dim3(NPIX / 64, BATCH_, NCLS_ / 16), 256, 65536>>>(out);
}

// round 7
// speedup vs baseline: 3.6708x; 3.6708x over previous
#include <cuda_runtime.h>
#include <cstdint>

#define NPIX   9216
#define HW_    96
#define CIN_   256
#define EMB1_  256
#define EMB2_  128
#define NCLS_  80
#define NEG_   3
#define BATCH_ 8

// ---------------- device scratch (allocation-free) ----------------
__device__ float g_xf [(size_t)BATCH_ * NPIX * CIN_];   // x NHWC, tf32-rounded fp32
__device__ float g_hf [(size_t)BATCH_ * NPIX * EMB1_];  // conv1+BN out, tf32-rounded fp32
__device__ float g_emb[(size_t)BATCH_ * NPIX * EMB2_];  // conv2 out, pixel-major fp32
__device__ float g_wf1[EMB1_ * 9 * 256];                // W1 as [co][tap][ci], tf32-rounded
__device__ float g_wf2[EMB2_ * 9 * 256];                // W2 same
__device__ float g_reps[NCLS_ * EMB2_];
__device__ float g_repsneg[NCLS_ * NEG_ * EMB2_];

// ---------------- helpers ----------------
__device__ __forceinline__ float to_tf32(float x) {
    uint32_t u;
    asm("cvt.rna.tf32.f32 %0, %1;" : "=r"(u) : "f"(x));
    return __uint_as_float(u);
}
#define MMA_TF32(d, a, b0, b1) \
    asm volatile("mma.sync.aligned.m16n8k8.row.col.f32.tf32.tf32.f32 " \
        "{%0,%1,%2,%3}, {%4,%5,%6,%7}, {%8,%9}, {%0,%1,%2,%3};" \
        : "+f"((d)[0]), "+f"((d)[1]), "+f"((d)[2]), "+f"((d)[3]) \
        : "r"((a)[0]), "r"((a)[1]), "r"((a)[2]), "r"((a)[3]), "r"(b0), "r"(b1))

// ---------------------------------------------------------------------------
// pre-pass: x NCHW fp32 -> NHWC tf32-rounded fp32
// ---------------------------------------------------------------------------
__global__ __launch_bounds__(256)
void transpose_x_kernel(const float* __restrict__ x)
{
    __shared__ float s32[256 * 33];
    const int tid = threadIdx.x;
    const int b = blockIdx.y;
    const int p0 = blockIdx.x * 32;
    const int pxr = tid & 31, chb = tid >> 5;
#pragma unroll 4
    for (int pass = 0; pass < 32; ++pass) {
        int ch = pass * 8 + chb;
        s32[ch * 33 + pxr] = to_tf32(x[((size_t)(b * 256 + ch)) * NPIX + p0 + pxr]);
    }
    __syncthreads();
    for (int px = 0; px < 32; ++px) {
        g_xf[((size_t)(b * NPIX + p0 + px)) * 256 + tid] = s32[tid * 33 + px];
    }
}

// ---------------------------------------------------------------------------
// pre-pass: W [co][256][3][3] fp32 -> [co][tap][ci] tf32-rounded fp32
// ---------------------------------------------------------------------------
__global__ __launch_bounds__(256)
void wprep_kernel(const float* __restrict__ w, float* __restrict__ dst, int total)
{
    int i = blockIdx.x * 256 + threadIdx.x;
    if (i >= total) return;
    int co = i / 2304, r = i - co * 2304;
    int t = r >> 8;
    int ci = r & 255;
    dst[i] = to_tf32(w[((size_t)(co * 256 + ci)) * 9 + t]);
}

// ---------------------------------------------------------------------------
// tf32 mma conv: 3x3 SAME, CI=256. Block = 128 co x 192 px (2 image rows).
// 8 warps = 4 co-quadrants x 2 image rows. Warp = 32co x 96px.
// Halo-amortized: X staged once per ci-chunk (4 rows x 98 cols), 9 taps
// read shifted offsets. Plain LDS fragment loads (no ldmatrix).
// STAGE 1: g_xf -> g_hf (BN folded). STAGE 2: g_hf -> g_emb (fp32 pm).
// ---------------------------------------------------------------------------
template<int STAGE>
__global__ __launch_bounds__(256)
void conv_tf32(const float* __restrict__ bias,
               const float* __restrict__ gamma,
               const float* __restrict__ beta,
               const float* __restrict__ mean,
               const float* __restrict__ var)
{
    extern __shared__ float smf[];
    float* Xh = smf;               // [4 rows][98 xpos][36 stride] = 14112 floats
    float* Ws = smf + 14112;       // [128 co][36 stride] = 4608 floats

    const int tid = threadIdx.x, wid = tid >> 5, lane = tid & 31;
    const int y0 = blockIdx.x * 2;
    const int b  = blockIdx.y;
    const int co0 = blockIdx.z * 128;
    const int wq = wid & 3, wh = wid >> 2;
    const int gid = lane >> 2, tig = lane & 3;

    const float* __restrict__ src  = (STAGE == 1) ? g_xf : g_hf;
    const float* __restrict__ wsrc = (STAGE == 1) ? g_wf1 : g_wf2;

    float acc[2][12][4];
#pragma unroll
    for (int m = 0; m < 2; ++m)
#pragma unroll
        for (int n = 0; n < 12; ++n)
#pragma unroll
            for (int q = 0; q < 4; ++q) acc[m][n][q] = 0.f;

    const uint32_t* Wsu = reinterpret_cast<const uint32_t*>(Ws);
    const uint32_t* Xhu = reinterpret_cast<const uint32_t*>(Xh);
    int aidx[2], xidx[12];
#pragma unroll
    for (int mi = 0; mi < 2; ++mi)
        aidx[mi] = (wq * 32 + mi * 16 + gid) * 36 + tig;
#pragma unroll
    for (int p = 0; p < 12; ++p)
        xidx[p] = (wh * 98 + p * 8 + gid) * 36 + tig;

    for (int c = 0; c < 8; ++c) {
        __syncthreads();
        // stage X halo: 4 image rows (y0-1..y0+2) x 98 xpos x 32 ci
        for (int i = tid; i < 3136; i += 256) {
            int pos = i >> 3, g = i & 7;
            int yrow = pos / 98, xpos = pos - yrow * 98;
            int y = y0 + yrow - 1, xc = xpos - 1;
            uint4 v = make_uint4(0u, 0u, 0u, 0u);
            if ((unsigned)y < 96u && (unsigned)xc < 96u)
                v = *reinterpret_cast<const uint4*>(
                    src + ((size_t)(b * NPIX + y * 96 + xc)) * 256 + c * 32 + g * 4);
            *reinterpret_cast<uint4*>(Xh + pos * 36 + g * 4) = v;
        }
        for (int tap = 0; tap < 9; ++tap) {
            const int kr = tap / 3, kc = tap - kr * 3;
            __syncthreads();   // previous tap done reading Ws (and, tap==0, Xh staged)
            for (int i = tid; i < 1024; i += 256) {
                int co = i >> 3, g = i & 7;
                uint4 v = *reinterpret_cast<const uint4*>(
                    wsrc + ((size_t)((co0 + co) * 9 + tap)) * 256 + c * 32 + g * 4);
                *reinterpret_cast<uint4*>(Ws + co * 36 + g * 4) = v;
            }
            __syncthreads();
            const int toff = (kr * 98 + kc) * 36;
#pragma unroll
            for (int ks = 0; ks < 4; ++ks) {
                const int k0 = ks * 8;
                uint32_t a[2][4];
#pragma unroll
                for (int mi = 0; mi < 2; ++mi) {
                    a[mi][0] = Wsu[aidx[mi] + k0];
                    a[mi][1] = Wsu[aidx[mi] + k0 + 8 * 36];
                    a[mi][2] = Wsu[aidx[mi] + k0 + 4];
                    a[mi][3] = Wsu[aidx[mi] + k0 + 8 * 36 + 4];
                }
#pragma unroll
                for (int p = 0; p < 12; ++p) {
                    uint32_t b0 = Xhu[xidx[p] + toff + k0];
                    uint32_t b1 = Xhu[xidx[p] + toff + k0 + 4];
                    MMA_TF32(acc[0][p], a[0], b0, b1);
                    MMA_TF32(acc[1][p], a[1], b0, b1);
                }
            }
        }
    }

    // ---- epilogue ----
    const size_t pixb = (size_t)b * NPIX + (size_t)(y0 + wh) * 96;
#pragma unroll
    for (int mi = 0; mi < 2; ++mi) {
        const int clo = co0 + wq * 32 + mi * 16 + gid;
        const int chi = clo + 8;
        float blo = bias[clo], bhi = bias[chi];
        float slo = 1.f, shi = 1.f, mlo = 0.f, mhi = 0.f, elo = 0.f, ehi = 0.f;
        if (STAGE == 1) {
            slo = gamma[clo] * rsqrtf(var[clo] + 1e-5f);
            shi = gamma[chi] * rsqrtf(var[chi] + 1e-5f);
            mlo = mean[clo]; mhi = mean[chi];
            elo = beta[clo]; ehi = beta[chi];
        }
#pragma unroll
        for (int n = 0; n < 12; ++n) {
            const int px0 = n * 8 + tig * 2;
#pragma unroll
            for (int j = 0; j < 2; ++j) {
                float vlo = acc[mi][n][j]     + blo;
                float vhi = acc[mi][n][j + 2] + bhi;
                const size_t pix = pixb + px0 + j;
                if (STAGE == 1) {
                    vlo = (vlo - mlo) * slo + elo;
                    vhi = (vhi - mhi) * shi + ehi;
                    g_hf[pix * 256 + clo] = to_tf32(vlo);
                    g_hf[pix * 256 + chi] = to_tf32(vhi);
                } else {
                    g_emb[pix * 128 + clo] = vlo;
                    g_emb[pix * 128 + chi] = vhi;
                }
            }
        }
    }
}

// ---------------------------------------------------------------------------
// L2-normalize emb (pixel-major), warp per pixel.
// ---------------------------------------------------------------------------
__global__ __launch_bounds__(256)
void normalize_emb_pm()
{
    const int gw = (blockIdx.x * 256 + threadIdx.x) >> 5;
    const int lane = threadIdx.x & 31;
    float4* e4 = reinterpret_cast<float4*>(g_emb + (size_t)gw * 128);
    float4 v = e4[lane];
    float ss = v.x * v.x + v.y * v.y + v.z * v.z + v.w * v.w;
#pragma unroll
    for (int o = 16; o > 0; o >>= 1) ss += __shfl_xor_sync(0xffffffffu, ss, o);
    float sc = 1.f / fmaxf(sqrtf(ss), 1e-12f);
    v.x *= sc; v.y *= sc; v.z *= sc; v.w *= sc;
    e4[lane] = v;
}

// ---------------------------------------------------------------------------
// reps prep (proven)
// ---------------------------------------------------------------------------
__device__ __forceinline__ float block_sumsq_128(float v, float* red4)
{
    float s = v * v;
#pragma unroll
    for (int o = 16; o > 0; o >>= 1) s += __shfl_xor_sync(0xffffffffu, s, o);
    const int wid = threadIdx.x >> 5, lane = threadIdx.x & 31;
    if (lane == 0) red4[wid] = s;
    __syncthreads();
    float tot = red4[0] + red4[1] + red4[2] + red4[3];
    __syncthreads();
    return tot;
}

__global__ __launch_bounds__(128)
void prep_reps_v3(const float* __restrict__ rep_w,
                  const float* __restrict__ rep_b,
                  const float* __restrict__ neg_w,
                  const float* __restrict__ neg_b)
{
    __shared__ float r_s[128];
    __shared__ float h_a[128];
    __shared__ float h_b[128];
    __shared__ float red4[4];

    const int j = threadIdx.x, c = blockIdx.x;

    float v = rep_w[c * 128 + j] + rep_b[c * 128 + j];
    float tot = block_sumsq_128(v, red4);
    float scale = 1.f / fmaxf(sqrtf(tot), 1e-12f);
    r_s[j] = v * scale;
    g_reps[c * 128 + j] = v * scale;
    __syncthreads();

    for (int n = 0; n < NEG_; ++n) {
        float accf = 0.f;
        const float* srcv = r_s;
#pragma unroll
        for (int i = 0; i < 3; ++i) {
            const float* W = neg_w + (size_t)((n * 3 + i) * 128) * 128;
            float acc = neg_b[(n * 3 + i) * 128 + j];
            for (int k = 0; k < 128; ++k)
                acc = fmaf(srcv[k], W[(size_t)j * 128 + k], acc);
            if (i < 2) {
                acc = fmaxf(acc, 0.f);
                float* dst = (i == 0) ? h_a : h_b;
                dst[j] = acc;
                __syncthreads();
                srcv = dst;
            } else {
                accf = acc;
            }
        }
        float t2 = block_sumsq_128(accf, red4);
        float sc2 = 1.f / fmaxf(sqrtf(t2), 1e-12f);
        g_repsneg[((size_t)c * NEG_ + n) * 128 + j] = accf * sc2;
        __syncthreads();
    }
}

// ---------------------------------------------------------------------------
// dot + epilogue: 64-px x 16-class tile; emb normalized, pixel-major source.
// ---------------------------------------------------------------------------
__global__ __launch_bounds__(256)
void dot_out_v4(float* __restrict__ out)
{
    extern __shared__ float smd[];
    float* e_s  = smd;                 // [128 ch][stride 68]
    float* rp_s = smd + 8704;          // [16 cls][128]
    float* rn_s = smd + 8704 + 2048;   // [16 cls][3][128]

    const int tid = threadIdx.x;
    const int b  = blockIdx.y;
    const int p0 = blockIdx.x * 64;
    const int c0 = blockIdx.z * 16;

    for (int i = tid; i < 8192; i += 256) {
        int px = i >> 7, ch = i & 127;
        e_s[ch * 68 + px] = g_emb[((size_t)(b * NPIX + p0 + px)) * 128 + ch];
    }
    for (int i = tid; i < 2048; i += 256) rp_s[i] = g_reps[c0 * EMB2_ + i];
    for (int i = tid; i < 6144; i += 256) rn_s[i] = g_repsneg[c0 * NEG_ * EMB2_ + i];
    __syncthreads();

    const int cc = tid >> 4;
    const int pg = tid & 15;
    const float* rpp = rp_s + cc * 128;
    const float* rn0 = rn_s + (cc * 3 + 0) * 128;
    const float* rn1 = rn_s + (cc * 3 + 1) * 128;
    const float* rn2 = rn_s + (cc * 3 + 2) * 128;

    float ap[4] = {0, 0, 0, 0};
    float a0[4] = {0, 0, 0, 0};
    float a1[4] = {0, 0, 0, 0};
    float a2[4] = {0, 0, 0, 0};

#pragma unroll 4
    for (int ch = 0; ch < 128; ++ch) {
        float4 ev = *reinterpret_cast<const float4*>(&e_s[ch * 68 + pg * 4]);
        float wp = rpp[ch], w0 = rn0[ch], w1 = rn1[ch], w2 = rn2[ch];
        ap[0] = fmaf(ev.x, wp, ap[0]); ap[1] = fmaf(ev.y, wp, ap[1]);
        ap[2] = fmaf(ev.z, wp, ap[2]); ap[3] = fmaf(ev.w, wp, ap[3]);
        a0[0] = fmaf(ev.x, w0, a0[0]); a0[1] = fmaf(ev.y, w0, a0[1]);
        a0[2] = fmaf(ev.z, w0, a0[2]); a0[3] = fmaf(ev.w, w0, a0[3]);
        a1[0] = fmaf(ev.x, w1, a1[0]); a1[1] = fmaf(ev.y, w1, a1[1]);
        a1[2] = fmaf(ev.z, w1, a1[2]); a1[3] = fmaf(ev.w, w1, a1[3]);
        a2[0] = fmaf(ev.x, w2, a2[0]); a2[1] = fmaf(ev.y, w2, a2[1]);
        a2[2] = fmaf(ev.z, w2, a2[2]); a2[3] = fmaf(ev.w, w2, a2[3]);
    }

    const int c = c0 + cc;
    const size_t S = (size_t)BATCH_ * NCLS_ * NPIX;
    float* out_cls  = out;
    float* out_csn  = out + S;
    float* out_dist = out + 2 * S;
    float* out_dneg = out + 3 * S;
    float* out_pori = out + 6 * S;

    const size_t base   = ((size_t)b * NCLS_ + c) * NPIX + p0 + pg * 4;
    const size_t dnbase = ((size_t)(b * NCLS_ + c) * 3) * NPIX + p0 + pg * 4;

#pragma unroll
    for (int jx = 0; jx < 4; ++jx) {
        float dist = sqrtf(fmaxf(2.f - 2.f * ap[jx], 0.f));
        float dn0  = sqrtf(fmaxf(2.f - 2.f * a0[jx], 0.f));
        float dn1  = sqrtf(fmaxf(2.f - 2.f * a1[jx], 0.f));
        float dn2  = sqrtf(fmaxf(2.f - 2.f * a2[jx], 0.f));

        float pn0 = expf(-dn0 * dn0 * 2.f);
        float pn1 = expf(-dn1 * dn1 * 2.f);
        float pn2 = expf(-dn2 * dn2 * 2.f);
        float csn = fmaxf(pn0, fmaxf(pn1, pn2));

        float minn = fminf(dn0, fminf(dn1, dn2));
        float shifted = dist + 0.3f * fmaxf(2.f - minn, 0.f);
        float pr = expf(-shifted * shifted * 2.f);
        float cs = fminf(fmaxf(pr, 0.f), 1.f);
        float cls = logf(fmaxf(cs, 1e-5f) / fmaxf(1.f - cs, 1e-5f));
        float pori = expf(-dist * dist * 2.f);

        out_cls [base + jx] = cls;
        out_csn [base + jx] = csn;
        out_dist[base + jx] = dist;
        out_pori[base + jx] = pori;
        out_dneg[dnbase + jx]            = dn0;
        out_dneg[dnbase + NPIX + jx]     = dn1;
        out_dneg[dnbase + 2 * NPIX + jx] = dn2;
    }
}

// ---------------------------------------------------------------------------
extern "C" void kernel_launch(void* const* d_in, const int* in_sizes, int n_in,
                              void* d_out, int out_size)
{
    const float* x      = (const float*)d_in[0];
    const float* w1     = (const float*)d_in[1];
    const float* b1     = (const float*)d_in[2];
    const float* gamma  = (const float*)d_in[3];
    const float* beta   = (const float*)d_in[4];
    const float* mean   = (const float*)d_in[5];
    const float* var    = (const float*)d_in[6];
    const float* w2     = (const float*)d_in[7];
    const float* b2     = (const float*)d_in[8];
    const float* rep_w  = (const float*)d_in[9];
    const float* rep_b  = (const float*)d_in[10];
    const float* neg_w  = (const float*)d_in[11];
    const float* neg_b  = (const float*)d_in[12];
    float* out = (float*)d_out;

    (void)in_sizes; (void)n_in; (void)out_size;

    const int CONV_SMEM = (14112 + 4608) * 4;   // 74880 B
    cudaFuncSetAttribute(conv_tf32<1>, cudaFuncAttributeMaxDynamicSharedMemorySize, CONV_SMEM);
    cudaFuncSetAttribute(conv_tf32<2>, cudaFuncAttributeMaxDynamicSharedMemorySize, CONV_SMEM);
    cudaFuncSetAttribute(dot_out_v4, cudaFuncAttributeMaxDynamicSharedMemorySize, 67584);

    float *wf1p, *wf2p;
    cudaGetSymbolAddress((void**)&wf1p, g_wf1);
    cudaGetSymbolAddress((void**)&wf2p, g_wf2);

    // pre-passes
    transpose_x_kernel<<<dim3(NPIX / 32, BATCH_), 256>>>(x);
    wprep_kernel<<<(EMB1_ * 2304 + 255) / 256, 256>>>(w1, wf1p, EMB1_ * 2304);
    wprep_kernel<<<(EMB2_ * 2304 + 255) / 256, 256>>>(w2, wf2p, EMB2_ * 2304);
    prep_reps_v3<<<NCLS_, 128>>>(rep_w, rep_b, neg_w, neg_b);

    // conv1 + BN (tf32 mma)
    conv_tf32<1><<<dim3(48, BATCH_, 2), 256, CONV_SMEM>>>(b1, gamma, beta, mean, var);
    // conv2 (tf32 mma)
    conv_tf32<2><<<dim3(48, BATCH_, 1), 256, CONV_SMEM>>>(b2, nullptr, nullptr, nullptr, nullptr);

    // normalize emb (pixel-major)
    normalize_emb_pm<<<BATCH_ * NPIX / 8, 256>>>();

    // fused dot + outputs
    dot_out_v4<<<dim3(NPIX / 64, BATCH_, NCLS_ / 16), 256, 67584>>>(out);
}